// round 5
// baseline (speedup 1.0000x reference)
#include <cuda_runtime.h>
#include <cuda_bf16.h>
#include <cstdint>

// ============================================================================
// Fused flash attention via mma.sync (HMMA, base sm_103 target):
//   O = dropout(softmax(Q K^T * sqrt(128))) V,  B=4, SEQ=4096, H=128, fp32.
// QK and PV as bf16 m16n8k16 MMAs with 3-way fp32-emulation splits.
// Dropout = JAX partitionable threefry2x32, key (0,42), bits = o1^o2,
// keep <=> bits < 7549747*512  (bit-exact, verified round 2).
// Round 5: BQ=64 / 128 threads / 2 CTAs/SM for cross-CTA latency hiding and
// full 148-SM coverage; MMA pass reorder to dep-distance 4.
// ============================================================================

namespace cfg {
constexpr int H = 128, SEQ = 4096, BQ = 64, BK = 64;
constexpr int NIT = SEQ / BK;                      // 64
constexpr int THREADS = 128;                       // 4 warps x 16 q-rows
constexpr uint32_t KEEP = 3865470464u;
constexpr float SCALE = 11.313708498984760390f;    // sqrt(128)
// padded bf16 smem tiles: row stride 136 elements = 272 bytes
constexpr int RS     = 272;
constexpr int QTILE  = BQ * RS;                    // 17408
constexpr int KTILE  = BK * RS;                    // 17408
constexpr int SM_QHI = 0;
constexpr int SM_QLO = SM_QHI + QTILE;
constexpr int SM_KHI = SM_QLO + QTILE;
constexpr int SM_KLO = SM_KHI + KTILE;
constexpr int SM_VHI = SM_KLO + KTILE;
constexpr int SM_VLO = SM_VHI + KTILE;
constexpr int SMEM_TOTAL = SM_VLO + KTILE;         // 104448 B  (x2 = 208896/SM)
}

// ---------------------------------------------------------------------------
// threefry-2x32-20, key (0,42), ctr (0,m) -> o1 ^ o2  (exact JAX partitionable)
#define TF_ROUND(a, b, r) { (a) += (b); (b) = __funnelshift_l((b), (b), (r)); (b) ^= (a); }
__device__ __forceinline__ uint32_t tf_bits(uint32_t b) {
    const uint32_t K1 = 42u, K2 = 0x1BD11BF0u;
    uint32_t a = 0u;
    b += K1;
    TF_ROUND(a,b,13) TF_ROUND(a,b,15) TF_ROUND(a,b,26) TF_ROUND(a,b,6)
    a += K1; b += K2 + 1u;
    TF_ROUND(a,b,17) TF_ROUND(a,b,29) TF_ROUND(a,b,16) TF_ROUND(a,b,24)
    a += K2; b += 2u;
    TF_ROUND(a,b,13) TF_ROUND(a,b,15) TF_ROUND(a,b,26) TF_ROUND(a,b,6)
    b += K1 + 3u;
    TF_ROUND(a,b,17) TF_ROUND(a,b,29) TF_ROUND(a,b,16) TF_ROUND(a,b,24)
    a += K1; b += K2 + 4u;
    TF_ROUND(a,b,13) TF_ROUND(a,b,15) TF_ROUND(a,b,26) TF_ROUND(a,b,6)
    a += K2; b += 5u;
    return a ^ b;
}

// ---------------------------------------------------------------------------
__device__ __forceinline__ uint32_t smem_u32(const void* p) {
    uint32_t a;
    asm("{ .reg .u64 t; cvta.to.shared.u64 t, %1; cvt.u32.u64 %0, t; }" : "=r"(a) : "l"(p));
    return a;
}
__device__ __forceinline__ void ldsm4(uint32_t* r, uint32_t addr) {
    asm volatile("ldmatrix.sync.aligned.m8n8.x4.shared.b16 {%0,%1,%2,%3}, [%4];"
                 : "=r"(r[0]), "=r"(r[1]), "=r"(r[2]), "=r"(r[3]) : "r"(addr));
}
__device__ __forceinline__ void ldsm4t(uint32_t* r, uint32_t addr) {
    asm volatile("ldmatrix.sync.aligned.m8n8.x4.trans.shared.b16 {%0,%1,%2,%3}, [%4];"
                 : "=r"(r[0]), "=r"(r[1]), "=r"(r[2]), "=r"(r[3]) : "r"(addr));
}
__device__ __forceinline__ void mma16816(float* d, const uint32_t* a, uint32_t b0, uint32_t b1) {
    asm volatile("mma.sync.aligned.m16n8k16.row.col.f32.bf16.bf16.f32 "
                 "{%0,%1,%2,%3}, {%4,%5,%6,%7}, {%8,%9}, {%0,%1,%2,%3};"
                 : "+f"(d[0]), "+f"(d[1]), "+f"(d[2]), "+f"(d[3])
                 : "r"(a[0]), "r"(a[1]), "r"(a[2]), "r"(a[3]), "r"(b0), "r"(b1));
}
__device__ __forceinline__ uint32_t pack2(__nv_bfloat16 x, __nv_bfloat16 y) {
    __nv_bfloat162 t; t.x = x; t.y = y;
    return *reinterpret_cast<uint32_t*>(&t);
}
__device__ __forceinline__ void split2(float x, float y, uint32_t& hi, uint32_t& lo) {
    __nv_bfloat16 hx = __float2bfloat16(x), hy = __float2bfloat16(y);
    hi = pack2(hx, hy);
    lo = pack2(__float2bfloat16(x - __bfloat162float(hx)),
               __float2bfloat16(y - __bfloat162float(hy)));
}

// ---------------------------------------------------------------------------
__global__ __launch_bounds__(cfg::THREADS, 2)
void attn_hmma_kernel(const float* __restrict__ Qg_,
                      const float* __restrict__ Kg_,
                      const float* __restrict__ Vg_,
                      float* __restrict__ Og) {
    using namespace cfg;
    extern __shared__ char smem[];
    const uint32_t sb = smem_u32(smem);

    const int tid  = threadIdx.x;
    const int wid  = tid >> 5;         // 0..3
    const int lane = tid & 31;
    const int qblk = blockIdx.x * BQ;
    const int bb   = blockIdx.y;

    const float* Qg = Qg_ + (size_t)bb * SEQ * H;
    const float* Kg = Kg_ + (size_t)bb * SEQ * H;
    const float* Vg = Vg_ + (size_t)bb * SEQ * H;

    // ---- load Q tile once (scaled), split to Qhi/Qlo smem ----
    #pragma unroll
    for (int i = 0; i < 16; ++i) {                 // 64 rows x 32 float4 / 128 thr
        int idx = tid + i * THREADS;
        int row = idx >> 5, c4 = (idx & 31) << 2;
        float4 v = *(const float4*)(Qg + (size_t)(qblk + row) * H + c4);
        v.x *= SCALE; v.y *= SCALE; v.z *= SCALE; v.w *= SCALE;
        uint32_t h0, l0, h1, l1;
        split2(v.x, v.y, h0, l0); split2(v.z, v.w, h1, l1);
        *(uint2*)(smem + SM_QHI + row * RS + c4 * 2) = make_uint2(h0, h1);
        *(uint2*)(smem + SM_QLO + row * RS + c4 * 2) = make_uint2(l0, l1);
    }

    // per-lane ldmatrix base addresses
    const uint32_t abase = sb + SM_QHI + (wid * 16 + (lane & 15)) * RS + (lane >> 4) * 16;
    const uint32_t bbase = sb + SM_KHI + (lane & 15) * RS + (lane >> 4) * 16;
    const uint32_t vbase = sb + SM_VHI + (lane & 15) * RS + (lane >> 4) * 16;

    float o[16][4];
    #pragma unroll
    for (int j = 0; j < 16; ++j)
        #pragma unroll
        for (int c = 0; c < 4; ++c) o[j][c] = 0.0f;
    float m0 = -1e30f, m1 = -1e30f, l0 = 0.0f, l1 = 0.0f;

    const int row_g0 = qblk + wid * 16 + (lane >> 2);
    const uint32_t mrow0 = ((uint32_t)bb << 24) | ((uint32_t)row_g0 << 12);
    const uint32_t mrow1 = mrow0 + (8u << 12);

    for (int it = 0; it < NIT; ++it) {
        const int vb = it * BK;
        __syncthreads();

        // ---- load K and V tiles (64x128 each), split ----
        #pragma unroll
        for (int i = 0; i < 16; ++i) {
            int idx = tid + i * THREADS;
            int row = idx >> 5, c4 = (idx & 31) << 2;
            float4 v = *(const float4*)(Kg + (size_t)(vb + row) * H + c4);
            uint32_t h0, lo0, h1, lo1;
            split2(v.x, v.y, h0, lo0); split2(v.z, v.w, h1, lo1);
            *(uint2*)(smem + SM_KHI + row * RS + c4 * 2) = make_uint2(h0, h1);
            *(uint2*)(smem + SM_KLO + row * RS + c4 * 2) = make_uint2(lo0, lo1);
        }
        #pragma unroll
        for (int i = 0; i < 16; ++i) {
            int idx = tid + i * THREADS;
            int row = idx >> 5, c4 = (idx & 31) << 2;
            float4 v = *(const float4*)(Vg + (size_t)(vb + row) * H + c4);
            uint32_t h0, lo0, h1, lo1;
            split2(v.x, v.y, h0, lo0); split2(v.z, v.w, h1, lo1);
            *(uint2*)(smem + SM_VHI + row * RS + c4 * 2) = make_uint2(h0, h1);
            *(uint2*)(smem + SM_VLO + row * RS + c4 * 2) = make_uint2(lo0, lo1);
        }
        __syncthreads();

        // ---- S = Qh*Kh + Qh*Kl + Ql*Kh  (16 x 64 per warp) ----
        // n-tiles processed in pairs -> each accumulator revisited at distance 4.
        float s[8][4];
        #pragma unroll
        for (int j = 0; j < 8; ++j)
            #pragma unroll
            for (int c = 0; c < 4; ++c) s[j][c] = 0.0f;

        #pragma unroll
        for (int ks = 0; ks < 8; ++ks) {
            uint32_t ah[4], al[4];
            ldsm4(ah, abase + ks * 32);
            ldsm4(al, abase + QTILE + ks * 32);
            #pragma unroll
            for (int np = 0; np < 2; ++np) {
                uint32_t bh0[4], bl0[4], bh1[4], bl1[4];
                ldsm4(bh0, bbase + (2*np)   * (16 * RS) + ks * 32);
                ldsm4(bl0, bbase + KTILE + (2*np)   * (16 * RS) + ks * 32);
                ldsm4(bh1, bbase + (2*np+1) * (16 * RS) + ks * 32);
                ldsm4(bl1, bbase + KTILE + (2*np+1) * (16 * RS) + ks * 32);
                float* s0 = s[4*np];   float* s1 = s[4*np+1];
                float* s2 = s[4*np+2]; float* s3 = s[4*np+3];
                // pass hh
                mma16816(s0, ah, bh0[0], bh0[2]);
                mma16816(s1, ah, bh0[1], bh0[3]);
                mma16816(s2, ah, bh1[0], bh1[2]);
                mma16816(s3, ah, bh1[1], bh1[3]);
                // pass hl
                mma16816(s0, ah, bl0[0], bl0[2]);
                mma16816(s1, ah, bl0[1], bl0[3]);
                mma16816(s2, ah, bl1[0], bl1[2]);
                mma16816(s3, ah, bl1[1], bl1[3]);
                // pass lh
                mma16816(s0, al, bh0[0], bh0[2]);
                mma16816(s1, al, bh0[1], bh0[3]);
                mma16816(s2, al, bh1[0], bh1[2]);
                mma16816(s3, al, bh1[1], bh1[3]);
            }
        }

        // ---- online softmax ----
        float mx0 = -1e30f, mx1 = -1e30f;
        #pragma unroll
        for (int j = 0; j < 8; ++j) {
            mx0 = fmaxf(mx0, fmaxf(s[j][0], s[j][1]));
            mx1 = fmaxf(mx1, fmaxf(s[j][2], s[j][3]));
        }
        #pragma unroll
        for (int off = 1; off < 4; off <<= 1) {
            mx0 = fmaxf(mx0, __shfl_xor_sync(0xffffffffu, mx0, off));
            mx1 = fmaxf(mx1, __shfl_xor_sync(0xffffffffu, mx1, off));
        }
        float mn0 = fmaxf(m0, mx0), mn1 = fmaxf(m1, mx1);
        float al0 = __expf(m0 - mn0), al1 = __expf(m1 - mn1);
        m0 = mn0; m1 = mn1;

        float ls0 = 0.0f, ls1 = 0.0f;
        #pragma unroll
        for (int j = 0; j < 8; ++j) {
            s[j][0] = __expf(s[j][0] - mn0); ls0 += s[j][0];
            s[j][1] = __expf(s[j][1] - mn0); ls0 += s[j][1];
            s[j][2] = __expf(s[j][2] - mn1); ls1 += s[j][2];
            s[j][3] = __expf(s[j][3] - mn1); ls1 += s[j][3];
        }
        #pragma unroll
        for (int off = 1; off < 4; off <<= 1) {
            ls0 += __shfl_xor_sync(0xffffffffu, ls0, off);
            ls1 += __shfl_xor_sync(0xffffffffu, ls1, off);
        }
        l0 = l0 * al0 + ls0;
        l1 = l1 * al1 + ls1;

        #pragma unroll
        for (int j = 0; j < 16; ++j) {
            o[j][0] *= al0; o[j][1] *= al0;
            o[j][2] *= al1; o[j][3] *= al1;
        }

        // ---- dropout (exact threefry) + build P hi/lo A-fragments ----
        uint32_t phi[4][4], plo[4][4];
        #pragma unroll
        for (int ks = 0; ks < 4; ++ks) {
            #pragma unroll
            for (int h2 = 0; h2 < 2; ++h2) {
                int j = 2 * ks + h2;
                uint32_t c = (uint32_t)(vb + j * 8 + (lane & 3) * 2);
                float p0 = (tf_bits(mrow0 + c)      < KEEP) ? s[j][0] : 0.0f;
                float p1 = (tf_bits(mrow0 + c + 1u) < KEEP) ? s[j][1] : 0.0f;
                float p2 = (tf_bits(mrow1 + c)      < KEEP) ? s[j][2] : 0.0f;
                float p3 = (tf_bits(mrow1 + c + 1u) < KEEP) ? s[j][3] : 0.0f;
                split2(p0, p1, phi[ks][h2 * 2],     plo[ks][h2 * 2]);
                split2(p2, p3, phi[ks][h2 * 2 + 1], plo[ks][h2 * 2 + 1]);
            }
        }

        // ---- O += Ph*Vh + Ph*Vl + Pl*Vh  (h-tiles in pairs, dep distance 4) ----
        #pragma unroll
        for (int ks = 0; ks < 4; ++ks) {
            #pragma unroll
            for (int hp = 0; hp < 4; ++hp) {
                uint32_t bh0[4], bl0[4], bh1[4], bl1[4];
                ldsm4t(bh0, vbase + ks * (16 * RS) + (2*hp)   * 32);
                ldsm4t(bl0, vbase + KTILE + ks * (16 * RS) + (2*hp)   * 32);
                ldsm4t(bh1, vbase + ks * (16 * RS) + (2*hp+1) * 32);
                ldsm4t(bl1, vbase + KTILE + ks * (16 * RS) + (2*hp+1) * 32);
                float* o0 = o[4*hp];   float* o1 = o[4*hp+1];
                float* o2 = o[4*hp+2]; float* o3 = o[4*hp+3];
                // pass Ph*Vh
                mma16816(o0, phi[ks], bh0[0], bh0[1]);
                mma16816(o1, phi[ks], bh0[2], bh0[3]);
                mma16816(o2, phi[ks], bh1[0], bh1[1]);
                mma16816(o3, phi[ks], bh1[2], bh1[3]);
                // pass Ph*Vl
                mma16816(o0, phi[ks], bl0[0], bl0[1]);
                mma16816(o1, phi[ks], bl0[2], bl0[3]);
                mma16816(o2, phi[ks], bl1[0], bl1[1]);
                mma16816(o3, phi[ks], bl1[2], bl1[3]);
                // pass Pl*Vh
                mma16816(o0, plo[ks], bh0[0], bh0[1]);
                mma16816(o1, plo[ks], bh0[2], bh0[3]);
                mma16816(o2, plo[ks], bh1[0], bh1[1]);
                mma16816(o3, plo[ks], bh1[2], bh1[3]);
            }
        }
    }

    // ---- epilogue: O /= (0.9 * l) ----
    float inv0 = 1.0f / (0.9f * l0);
    float inv1 = 1.0f / (0.9f * l1);
    float* out0 = Og + ((size_t)bb * SEQ + row_g0) * H;
    float* out1 = out0 + 8 * H;
    #pragma unroll
    for (int j = 0; j < 16; ++j) {
        int h = j * 8 + (lane & 3) * 2;
        *(float2*)(out0 + h) = make_float2(o[j][0] * inv0, o[j][1] * inv0);
        *(float2*)(out1 + h) = make_float2(o[j][2] * inv1, o[j][3] * inv1);
    }
}

extern "C" void kernel_launch(void* const* d_in, const int* in_sizes, int n_in,
                              void* d_out, int out_size) {
    const float* Q = (const float*)d_in[0];
    const float* K = (const float*)d_in[1];
    const float* V = (const float*)d_in[2];
    float* O = (float*)d_out;
    (void)in_sizes; (void)n_in; (void)out_size;

    cudaFuncSetAttribute(attn_hmma_kernel,
                         cudaFuncAttributeMaxDynamicSharedMemorySize, cfg::SMEM_TOTAL);
    dim3 grid(cfg::SEQ / cfg::BQ, 4);
    attn_hmma_kernel<<<grid, cfg::THREADS, cfg::SMEM_TOTAL>>>(Q, K, V, O);
}

// round 6
// speedup vs baseline: 1.1366x; 1.1366x over previous
#include <cuda_runtime.h>
#include <cuda_bf16.h>
#include <cstdint>

// ============================================================================
// Fused flash attention via mma.sync (HMMA, base sm_103 target):
//   O = dropout(softmax(Q K^T * sqrt(128))) V,  B=4, SEQ=4096, H=128, fp32.
// QK and PV as bf16 m16n8k16 MMAs with 3-way fp32-emulation splits.
// Dropout = JAX partitionable threefry2x32, key (0,42), bits = o1^o2,
// keep <=> bits < 7549747*512  (bit-exact, verified round 2).
// Round 6: BQ=128 (round-4 base) + double-buffered K/V with ONE barrier/iter,
// 8-way interleaved threefry, bf16x2-pack split (bitwise identical math).
// ============================================================================

namespace cfg {
constexpr int H = 128, SEQ = 4096, BQ = 128, BK = 64;
constexpr int NIT = SEQ / BK;                      // 64
constexpr int THREADS = 256;
constexpr uint32_t KEEP = 3865470464u;
constexpr float SCALE = 11.313708498984760390f;    // sqrt(128)
constexpr int RS     = 272;                        // bf16 row stride bytes (136 elem)
constexpr int QTILE  = BQ * RS;                    // 34816
constexpr int KTILE  = BK * RS;                    // 17408
constexpr int SM_QHI = 0;
constexpr int SM_QLO = QTILE;
constexpr int SM_BUF0 = 2 * QTILE;                 // 69632
// buffer layout: KHI | KLO | VHI | VLO, each KTILE
constexpr int BUFSZ  = 4 * KTILE;                  // 69632
constexpr int SMEM_TOTAL = SM_BUF0 + 2 * BUFSZ;    // 208896 B
}

// ---------------------------------------------------------------------------
// 8-way interleaved threefry-2x32-20, key (0,42), ctr (0,m) -> o1^o2
__device__ __forceinline__ void tf8(const uint32_t* ctr, uint32_t* out) {
    const uint32_t K1 = 42u, K2 = 0x1BD11BF0u;
    uint32_t a[8], b[8];
    #pragma unroll
    for (int j = 0; j < 8; ++j) { a[j] = 0u; b[j] = ctr[j] + K1; }
#define R8(r) \
    _Pragma("unroll") \
    for (int j = 0; j < 8; ++j) { \
        a[j] += b[j]; b[j] = __funnelshift_l(b[j], b[j], (r)); b[j] ^= a[j]; }
#define I8(ka, kb) \
    _Pragma("unroll") \
    for (int j = 0; j < 8; ++j) { a[j] += (ka); b[j] += (kb); }
    R8(13) R8(15) R8(26) R8(6)
    I8(K1, K2 + 1u)
    R8(17) R8(29) R8(16) R8(24)
    I8(K2, 2u)
    R8(13) R8(15) R8(26) R8(6)
    I8(0u, K1 + 3u)
    R8(17) R8(29) R8(16) R8(24)
    I8(K1, K2 + 4u)
    R8(13) R8(15) R8(26) R8(6)
    I8(K2, 5u)
#undef R8
#undef I8
    #pragma unroll
    for (int j = 0; j < 8; ++j) out[j] = a[j] ^ b[j];
}

// ---------------------------------------------------------------------------
__device__ __forceinline__ uint32_t smem_u32(const void* p) {
    uint32_t a;
    asm("{ .reg .u64 t; cvta.to.shared.u64 t, %1; cvt.u32.u64 %0, t; }" : "=r"(a) : "l"(p));
    return a;
}
__device__ __forceinline__ void ldsm4(uint32_t* r, uint32_t addr) {
    asm volatile("ldmatrix.sync.aligned.m8n8.x4.shared.b16 {%0,%1,%2,%3}, [%4];"
                 : "=r"(r[0]), "=r"(r[1]), "=r"(r[2]), "=r"(r[3]) : "r"(addr));
}
__device__ __forceinline__ void ldsm4t(uint32_t* r, uint32_t addr) {
    asm volatile("ldmatrix.sync.aligned.m8n8.x4.trans.shared.b16 {%0,%1,%2,%3}, [%4];"
                 : "=r"(r[0]), "=r"(r[1]), "=r"(r[2]), "=r"(r[3]) : "r"(addr));
}
__device__ __forceinline__ void mma16816(float* d, const uint32_t* a, uint32_t b0, uint32_t b1) {
    asm volatile("mma.sync.aligned.m16n8k16.row.col.f32.bf16.bf16.f32 "
                 "{%0,%1,%2,%3}, {%4,%5,%6,%7}, {%8,%9}, {%0,%1,%2,%3};"
                 : "+f"(d[0]), "+f"(d[1]), "+f"(d[2]), "+f"(d[3])
                 : "r"(a[0]), "r"(a[1]), "r"(a[2]), "r"(a[3]), "r"(b0), "r"(b1));
}
// split (x,y) -> hi bf16x2 pack, lo bf16x2 pack.  Bitwise identical to the
// __float2bfloat16 sequence: hi = rn(x); lo = rn(x - (hi<<16)).
__device__ __forceinline__ void split2f(float x, float y, uint32_t& hi, uint32_t& lo) {
    uint32_t h;
    asm("cvt.rn.bf16x2.f32 %0, %1, %2;" : "=r"(h) : "f"(y), "f"(x));
    float fx = __uint_as_float(h << 16);
    float fy = __uint_as_float(h & 0xffff0000u);
    uint32_t l;
    asm("cvt.rn.bf16x2.f32 %0, %1, %2;" : "=r"(l) : "f"(y - fy), "f"(x - fx));
    hi = h; lo = l;
}

// ---------------------------------------------------------------------------
__global__ __launch_bounds__(cfg::THREADS, 1)
void attn_hmma_kernel(const float* __restrict__ Qg_,
                      const float* __restrict__ Kg_,
                      const float* __restrict__ Vg_,
                      float* __restrict__ Og) {
    using namespace cfg;
    extern __shared__ char smem[];
    const uint32_t sb = smem_u32(smem);

    const int tid  = threadIdx.x;
    const int wid  = tid >> 5;
    const int lane = tid & 31;
    const int qblk = blockIdx.x * BQ;
    const int bb   = blockIdx.y;

    const float* Qg = Qg_ + (size_t)bb * SEQ * H;
    const float* Kg = Kg_ + (size_t)bb * SEQ * H;
    const float* Vg = Vg_ + (size_t)bb * SEQ * H;

    // ---- load Q tile once (scaled), split to Qhi/Qlo smem ----
    #pragma unroll
    for (int i = 0; i < 16; ++i) {                 // 128 rows x 32 float4
        int idx = tid + i * THREADS;
        int row = idx >> 5, c4 = (idx & 31) << 2;
        float4 v = *(const float4*)(Qg + (size_t)(qblk + row) * H + c4);
        v.x *= SCALE; v.y *= SCALE; v.z *= SCALE; v.w *= SCALE;
        uint32_t h0, l0, h1, l1;
        split2f(v.x, v.y, h0, l0); split2f(v.z, v.w, h1, l1);
        *(uint2*)(smem + SM_QHI + row * RS + c4 * 2) = make_uint2(h0, h1);
        *(uint2*)(smem + SM_QLO + row * RS + c4 * 2) = make_uint2(l0, l1);
    }

    // ---- prologue: prefetch K/V tile 0 into buffer 0 ----
    {
        float4 kv4[8];
        #pragma unroll
        for (int i = 0; i < 8; ++i) {
            int idx = tid + i * THREADS;
            kv4[i] = *(const float4*)(Kg + (size_t)(idx >> 5) * H + ((idx & 31) << 2));
        }
        #pragma unroll
        for (int i = 0; i < 8; ++i) {
            int idx = tid + i * THREADS;
            int row = idx >> 5, c4 = (idx & 31) << 2;
            uint32_t h0, l0, h1, l1;
            split2f(kv4[i].x, kv4[i].y, h0, l0); split2f(kv4[i].z, kv4[i].w, h1, l1);
            *(uint2*)(smem + SM_BUF0 + row * RS + c4 * 2) = make_uint2(h0, h1);
            *(uint2*)(smem + SM_BUF0 + KTILE + row * RS + c4 * 2) = make_uint2(l0, l1);
        }
        #pragma unroll
        for (int i = 0; i < 8; ++i) {
            int idx = tid + i * THREADS;
            kv4[i] = *(const float4*)(Vg + (size_t)(idx >> 5) * H + ((idx & 31) << 2));
        }
        #pragma unroll
        for (int i = 0; i < 8; ++i) {
            int idx = tid + i * THREADS;
            int row = idx >> 5, c4 = (idx & 31) << 2;
            uint32_t h0, l0, h1, l1;
            split2f(kv4[i].x, kv4[i].y, h0, l0); split2f(kv4[i].z, kv4[i].w, h1, l1);
            *(uint2*)(smem + SM_BUF0 + 2 * KTILE + row * RS + c4 * 2) = make_uint2(h0, h1);
            *(uint2*)(smem + SM_BUF0 + 3 * KTILE + row * RS + c4 * 2) = make_uint2(l0, l1);
        }
    }

    // per-lane ldmatrix lane offsets
    const uint32_t abase   = sb + SM_QHI + (wid * 16 + (lane & 15)) * RS + (lane >> 4) * 16;
    const uint32_t kb_lane = (lane & 15) * RS + (lane >> 4) * 16;

    float o[16][4];
    #pragma unroll
    for (int j = 0; j < 16; ++j)
        #pragma unroll
        for (int c = 0; c < 4; ++c) o[j][c] = 0.0f;
    float m0 = -1e30f, m1 = -1e30f, l0 = 0.0f, l1 = 0.0f;

    const int row_g0 = qblk + wid * 16 + (lane >> 2);
    const uint32_t mrow0 = ((uint32_t)bb << 24) | ((uint32_t)row_g0 << 12);
    const uint32_t mrow1 = mrow0 + (8u << 12);

    for (int it = 0; it < NIT; ++it) {
        const int vb = it * BK;
        __syncthreads();   // buf[it&1] writes visible; prior reads of buf[(it+1)&1] done

        // ---- prefetch K/V tile it+1 into the other buffer (no barrier after) ----
        if (it + 1 < NIT) {
            const int vb2 = vb + BK;
            char* bufn = smem + SM_BUF0 + ((it + 1) & 1) * BUFSZ;
            float4 kv4[8];
            #pragma unroll
            for (int i = 0; i < 8; ++i) {
                int idx = tid + i * THREADS;
                kv4[i] = *(const float4*)(Kg + (size_t)(vb2 + (idx >> 5)) * H + ((idx & 31) << 2));
            }
            #pragma unroll
            for (int i = 0; i < 8; ++i) {
                int idx = tid + i * THREADS;
                int row = idx >> 5, c4 = (idx & 31) << 2;
                uint32_t h0, l0_, h1, l1_;
                split2f(kv4[i].x, kv4[i].y, h0, l0_); split2f(kv4[i].z, kv4[i].w, h1, l1_);
                *(uint2*)(bufn + row * RS + c4 * 2) = make_uint2(h0, h1);
                *(uint2*)(bufn + KTILE + row * RS + c4 * 2) = make_uint2(l0_, l1_);
            }
            #pragma unroll
            for (int i = 0; i < 8; ++i) {
                int idx = tid + i * THREADS;
                kv4[i] = *(const float4*)(Vg + (size_t)(vb2 + (idx >> 5)) * H + ((idx & 31) << 2));
            }
            #pragma unroll
            for (int i = 0; i < 8; ++i) {
                int idx = tid + i * THREADS;
                int row = idx >> 5, c4 = (idx & 31) << 2;
                uint32_t h0, l0_, h1, l1_;
                split2f(kv4[i].x, kv4[i].y, h0, l0_); split2f(kv4[i].z, kv4[i].w, h1, l1_);
                *(uint2*)(bufn + 2 * KTILE + row * RS + c4 * 2) = make_uint2(h0, h1);
                *(uint2*)(bufn + 3 * KTILE + row * RS + c4 * 2) = make_uint2(l0_, l1_);
            }
        }

        const uint32_t bufc = sb + SM_BUF0 + (uint32_t)((it & 1) * BUFSZ);
        const uint32_t bK = bufc + kb_lane;              // Khi (lo at +KTILE)
        const uint32_t bV = bufc + 2 * KTILE + kb_lane;  // Vhi (lo at +KTILE)

        // ---- S = Qh*Kh + Qh*Kl + Ql*Kh  (16 x 64 per warp, dep distance 4) ----
        float s[8][4];
        #pragma unroll
        for (int j = 0; j < 8; ++j)
            #pragma unroll
            for (int c = 0; c < 4; ++c) s[j][c] = 0.0f;

        #pragma unroll
        for (int ks = 0; ks < 8; ++ks) {
            uint32_t ah[4], al[4];
            ldsm4(ah, abase + ks * 32);
            ldsm4(al, abase + QTILE + ks * 32);
            #pragma unroll
            for (int np = 0; np < 2; ++np) {
                uint32_t bh0[4], bl0[4], bh1[4], bl1[4];
                ldsm4(bh0, bK + (2 * np) * (16 * RS) + ks * 32);
                ldsm4(bl0, bK + KTILE + (2 * np) * (16 * RS) + ks * 32);
                ldsm4(bh1, bK + (2 * np + 1) * (16 * RS) + ks * 32);
                ldsm4(bl1, bK + KTILE + (2 * np + 1) * (16 * RS) + ks * 32);
                float* s0 = s[4 * np];     float* s1 = s[4 * np + 1];
                float* s2 = s[4 * np + 2]; float* s3 = s[4 * np + 3];
                mma16816(s0, ah, bh0[0], bh0[2]);
                mma16816(s1, ah, bh0[1], bh0[3]);
                mma16816(s2, ah, bh1[0], bh1[2]);
                mma16816(s3, ah, bh1[1], bh1[3]);
                mma16816(s0, ah, bl0[0], bl0[2]);
                mma16816(s1, ah, bl0[1], bl0[3]);
                mma16816(s2, ah, bl1[0], bl1[2]);
                mma16816(s3, ah, bl1[1], bl1[3]);
                mma16816(s0, al, bh0[0], bh0[2]);
                mma16816(s1, al, bh0[1], bh0[3]);
                mma16816(s2, al, bh1[0], bh1[2]);
                mma16816(s3, al, bh1[1], bh1[3]);
            }
        }

        // ---- online softmax ----
        float mx0 = -1e30f, mx1 = -1e30f;
        #pragma unroll
        for (int j = 0; j < 8; ++j) {
            mx0 = fmaxf(mx0, fmaxf(s[j][0], s[j][1]));
            mx1 = fmaxf(mx1, fmaxf(s[j][2], s[j][3]));
        }
        #pragma unroll
        for (int off = 1; off < 4; off <<= 1) {
            mx0 = fmaxf(mx0, __shfl_xor_sync(0xffffffffu, mx0, off));
            mx1 = fmaxf(mx1, __shfl_xor_sync(0xffffffffu, mx1, off));
        }
        float mn0 = fmaxf(m0, mx0), mn1 = fmaxf(m1, mx1);
        float al0 = __expf(m0 - mn0), al1 = __expf(m1 - mn1);
        m0 = mn0; m1 = mn1;

        float ls0 = 0.0f, ls1 = 0.0f;
        #pragma unroll
        for (int j = 0; j < 8; ++j) {
            s[j][0] = __expf(s[j][0] - mn0); ls0 += s[j][0];
            s[j][1] = __expf(s[j][1] - mn0); ls0 += s[j][1];
            s[j][2] = __expf(s[j][2] - mn1); ls1 += s[j][2];
            s[j][3] = __expf(s[j][3] - mn1); ls1 += s[j][3];
        }
        #pragma unroll
        for (int off = 1; off < 4; off <<= 1) {
            ls0 += __shfl_xor_sync(0xffffffffu, ls0, off);
            ls1 += __shfl_xor_sync(0xffffffffu, ls1, off);
        }
        l0 = l0 * al0 + ls0;
        l1 = l1 * al1 + ls1;

        #pragma unroll
        for (int j = 0; j < 16; ++j) {
            o[j][0] *= al0; o[j][1] *= al0;
            o[j][2] *= al1; o[j][3] *= al1;
        }

        // ---- dropout (8-way interleaved threefry) + P hi/lo fragments ----
        uint32_t phi[4][4], plo[4][4];
        #pragma unroll
        for (int ks = 0; ks < 4; ++ks) {
            uint32_t ctr[8], bits[8];
            #pragma unroll
            for (int h2 = 0; h2 < 2; ++h2) {
                uint32_t c = (uint32_t)(vb + (2 * ks + h2) * 8 + (lane & 3) * 2);
                ctr[h2 * 4 + 0] = mrow0 + c;
                ctr[h2 * 4 + 1] = mrow0 + c + 1u;
                ctr[h2 * 4 + 2] = mrow1 + c;
                ctr[h2 * 4 + 3] = mrow1 + c + 1u;
            }
            tf8(ctr, bits);
            #pragma unroll
            for (int h2 = 0; h2 < 2; ++h2) {
                int j = 2 * ks + h2;
                float p0 = (bits[h2 * 4 + 0] < KEEP) ? s[j][0] : 0.0f;
                float p1 = (bits[h2 * 4 + 1] < KEEP) ? s[j][1] : 0.0f;
                float p2 = (bits[h2 * 4 + 2] < KEEP) ? s[j][2] : 0.0f;
                float p3 = (bits[h2 * 4 + 3] < KEEP) ? s[j][3] : 0.0f;
                split2f(p0, p1, phi[ks][h2 * 2],     plo[ks][h2 * 2]);
                split2f(p2, p3, phi[ks][h2 * 2 + 1], plo[ks][h2 * 2 + 1]);
            }
        }

        // ---- O += Ph*Vh + Ph*Vl + Pl*Vh  (dep distance 4) ----
        #pragma unroll
        for (int ks = 0; ks < 4; ++ks) {
            #pragma unroll
            for (int hp = 0; hp < 4; ++hp) {
                uint32_t bh0[4], bl0[4], bh1[4], bl1[4];
                ldsm4t(bh0, bV + ks * (16 * RS) + (2 * hp) * 32);
                ldsm4t(bl0, bV + KTILE + ks * (16 * RS) + (2 * hp) * 32);
                ldsm4t(bh1, bV + ks * (16 * RS) + (2 * hp + 1) * 32);
                ldsm4t(bl1, bV + KTILE + ks * (16 * RS) + (2 * hp + 1) * 32);
                float* o0 = o[4 * hp];     float* o1 = o[4 * hp + 1];
                float* o2 = o[4 * hp + 2]; float* o3 = o[4 * hp + 3];
                mma16816(o0, phi[ks], bh0[0], bh0[1]);
                mma16816(o1, phi[ks], bh0[2], bh0[3]);
                mma16816(o2, phi[ks], bh1[0], bh1[1]);
                mma16816(o3, phi[ks], bh1[2], bh1[3]);
                mma16816(o0, phi[ks], bl0[0], bl0[1]);
                mma16816(o1, phi[ks], bl0[2], bl0[3]);
                mma16816(o2, phi[ks], bl1[0], bl1[1]);
                mma16816(o3, phi[ks], bl1[2], bl1[3]);
                mma16816(o0, plo[ks], bh0[0], bh0[1]);
                mma16816(o1, plo[ks], bh0[2], bh0[3]);
                mma16816(o2, plo[ks], bh1[0], bh1[1]);
                mma16816(o3, plo[ks], bh1[2], bh1[3]);
            }
        }
    }

    // ---- epilogue: O /= (0.9 * l) ----
    float inv0 = 1.0f / (0.9f * l0);
    float inv1 = 1.0f / (0.9f * l1);
    float* out0 = Og + ((size_t)bb * SEQ + row_g0) * H;
    float* out1 = out0 + 8 * H;
    #pragma unroll
    for (int j = 0; j < 16; ++j) {
        int h = j * 8 + (lane & 3) * 2;
        *(float2*)(out0 + h) = make_float2(o[j][0] * inv0, o[j][1] * inv0);
        *(float2*)(out1 + h) = make_float2(o[j][2] * inv1, o[j][3] * inv1);
    }
}

extern "C" void kernel_launch(void* const* d_in, const int* in_sizes, int n_in,
                              void* d_out, int out_size) {
    const float* Q = (const float*)d_in[0];
    const float* K = (const float*)d_in[1];
    const float* V = (const float*)d_in[2];
    float* O = (float*)d_out;
    (void)in_sizes; (void)n_in; (void)out_size;

    cudaFuncSetAttribute(attn_hmma_kernel,
                         cudaFuncAttributeMaxDynamicSharedMemorySize, cfg::SMEM_TOTAL);
    dim3 grid(cfg::SEQ / cfg::BQ, 4);
    attn_hmma_kernel<<<grid, cfg::THREADS, cfg::SMEM_TOTAL>>>(Q, K, V, O);
}